// round 13
// baseline (speedup 1.0000x reference)
#include <cuda_runtime.h>
#include <cuda_bf16.h>
#include <stdint.h>

#define NN 4096
#define DD 256
#define BM 128
#define SA 264          // bf16 elems per padded smem row (256+8)
#define NUNITS 528      // upper-triangular (rt <= ch) units
#define GRID 148
#define INV_T 14.285714285714286f

// smem: A | B0 | B1 | bit tiles (2 bufs x [tileN pm|nm | tileT pm|nm] x 512 words)
#define BITS_OFF 202752
#define SMEM_TOTAL (202752 + 16384)

// scratch (device globals; unwritten slots stay zero -> safe to read)
__device__ __nv_bfloat16 g_fn[NN * DD];
__device__ float g_negP[NN * 64];    // [row][ch*2+wn]
__device__ float g_pcsP[NN * 64];
__device__ float g_cntP[NN * 64];
__device__ float g_negT[NN * 128];   // [row][rt*4+wm]
__device__ float g_pcsT[NN * 128];
__device__ float g_cntT[NN * 128];
__device__ float g_blockSum[16];
__device__ unsigned g_ctr = 0;       // self-resetting via atomicInc wrap

// ---------------------------------------------------------------------------
__device__ __forceinline__ float fast_expf(float x) {
    float y = x * 1.4426950408889634f;
    float n = rintf(y);
    float f = y - n;
    float p = 1.3333558146e-3f;
    p = fmaf(p, f, 9.6181291076e-3f);
    p = fmaf(p, f, 5.5504108664e-2f);
    p = fmaf(p, f, 2.4022650696e-1f);
    p = fmaf(p, f, 6.9314718056e-1f);
    p = fmaf(p, f, 1.0f);
    int ni = (int)n;
    return p * __int_as_float((ni + 127) << 23);
}

__device__ __forceinline__ void cp16(void* s, const void* g) {
    uint32_t sa = (uint32_t)__cvta_generic_to_shared(s);
    asm volatile("cp.async.cg.shared.global [%0], [%1], 16;\n" :: "r"(sa), "l"(g));
}
__device__ __forceinline__ void cp_commit()  { asm volatile("cp.async.commit_group;\n" ::: "memory"); }
__device__ __forceinline__ void cp_wait_all(){ asm volatile("cp.async.wait_group 0;\n" ::: "memory"); }

__device__ __forceinline__ void ldsm_x4(uint32_t& r0, uint32_t& r1, uint32_t& r2,
                                        uint32_t& r3, uint32_t saddr) {
    asm volatile("ldmatrix.sync.aligned.m8n8.x4.shared.b16 {%0,%1,%2,%3}, [%4];"
                 : "=r"(r0), "=r"(r1), "=r"(r2), "=r"(r3) : "r"(saddr));
}

// decode linear unit v -> (rt, ch), enumeration: rt ascending, ch = rt..31
__device__ __forceinline__ void decode_unit(int v, int& rt, int& ch) {
    int r = 0;
    while (v >= 32 - r && r < 32) { v -= 32 - r; r++; }
    rt = r; ch = r + v;
}

// ---- mask pack: steps s in [0, nsteps); region=s>>5 (0:N=(rt,ch), 1:T=(ch,rt)),
//      mask=(s>>4)&1 (0:pm,1:nm), row-iter i=s&15; warp w owns rows w*16+i.
// bit tile layout: word rowLocal*4 + (col&3), bit col>>2.
__device__ __forceinline__ void pack_issue(float4* pk, const float* pmask,
                                           const float* nmask, int w0,
                                           int rtN, int chN, int warp, int lane) {
#pragma unroll
    for (int k = 0; k < 8; k++) {
        int s = w0 + k;
        int region = s >> 5;
        const float* base = (s & 16) ? nmask : pmask;
        int rb = region ? chN : rtN;
        int cb = region ? rtN : chN;
        const float* src = base + (size_t)(rb * 128 + warp * 16 + (s & 15)) * NN
                         + cb * 128 + lane * 4;
        pk[k] = __ldcs((const float4*)src);
    }
}
__device__ __forceinline__ void pack_consume(const float4* pk, uint32_t* bits,
                                             int w0, int warp, int lane) {
#pragma unroll
    for (int k = 0; k < 8; k++) {
        int s = w0 + k;
        uint32_t b0 = __ballot_sync(0xffffffffu, pk[k].x != 0.f);
        uint32_t b1 = __ballot_sync(0xffffffffu, pk[k].y != 0.f);
        uint32_t b2 = __ballot_sync(0xffffffffu, pk[k].z != 0.f);
        uint32_t b3 = __ballot_sync(0xffffffffu, pk[k].w != 0.f);
        if (lane == 0) {
            int region = s >> 5, m = (s >> 4) & 1, i = s & 15;
            *(uint4*)&bits[region * 1024 + m * 512 + (warp * 16 + i) * 4]
                = make_uint4(b0, b1, b2, b3);
        }
    }
}

// ---------------------------------------------------------------------------
// Kernel 1: row-normalize features -> bf16
// ---------------------------------------------------------------------------
__global__ void __launch_bounds__(256) normalize_kernel(const float* __restrict__ f) {
    int row  = blockIdx.x * 8 + (threadIdx.x >> 5);
    int lane = threadIdx.x & 31;
    const float4* src = (const float4*)(f + (size_t)row * DD);
    float4 v0 = src[lane * 2];
    float4 v1 = src[lane * 2 + 1];
    float ss = v0.x * v0.x;
    ss = fmaf(v0.y, v0.y, ss); ss = fmaf(v0.z, v0.z, ss); ss = fmaf(v0.w, v0.w, ss);
    ss = fmaf(v1.x, v1.x, ss); ss = fmaf(v1.y, v1.y, ss);
    ss = fmaf(v1.z, v1.z, ss); ss = fmaf(v1.w, v1.w, ss);
#pragma unroll
    for (int o = 16; o; o >>= 1) ss += __shfl_xor_sync(0xffffffffu, ss, o);
    float s = 1.0f / fmaxf(sqrtf(ss), 1e-8f);
    __nv_bfloat162 h[4];
    h[0] = __floats2bfloat162_rn(v0.x * s, v0.y * s);
    h[1] = __floats2bfloat162_rn(v0.z * s, v0.w * s);
    h[2] = __floats2bfloat162_rn(v1.x * s, v1.y * s);
    h[3] = __floats2bfloat162_rn(v1.z * s, v1.w * s);
    *(uint4*)&g_fn[(size_t)row * DD + lane * 8] = *(uint4*)h;
}

// ---------------------------------------------------------------------------
// Kernel 2: symmetric persistent GEMM. Only rt<=ch units; off-diagonal units
// run the epilogue twice (normal + transposed on the same fragments).
// ---------------------------------------------------------------------------
__global__ void __launch_bounds__(256, 1)
ssntx_main_kernel(const float* __restrict__ pmask, const float* __restrict__ nmask) {
    extern __shared__ unsigned char smem[];
    __nv_bfloat16* As = (__nv_bfloat16*)smem;
    __nv_bfloat16* B0 = (__nv_bfloat16*)(smem + BM * SA * 2);
    __nv_bfloat16* B1 = (__nv_bfloat16*)(smem + 2 * BM * SA * 2);
    uint32_t* bitsAll = (uint32_t*)(smem + BITS_OFF);   // [buf][2048 words]

    const int tid  = threadIdx.x;
    const int lane = tid & 31;
    const int warp = tid >> 5;
    const int g    = lane >> 2;
    const int tg   = lane & 3;
    const int wm   = warp >> 1;
    const int wn   = warp & 1;

    const int vStart = (int)(((long long)blockIdx.x       * NUNITS) / GRID);
    const int vEnd   = (int)(((long long)(blockIdx.x + 1) * NUNITS) / GRID);

    const uint32_t asBase = (uint32_t)__cvta_generic_to_shared(As);
    const uint32_t b0Base = (uint32_t)__cvta_generic_to_shared(B0);
    const uint32_t b1Base = (uint32_t)__cvta_generic_to_shared(B1);
    const uint32_t lmCol  = (uint32_t)((lane >> 4) * 8) * 2;
    uint32_t aOff[2], bOff[4];
#pragma unroll
    for (int mi = 0; mi < 2; mi++)
        aOff[mi] = (uint32_t)((wm * 32 + mi * 16 + (lane & 15)) * SA) * 2 + lmCol;
#pragma unroll
    for (int p = 0; p < 4; p++)
        bOff[p] = (uint32_t)((wn * 64 + p * 16 + (lane & 15)) * SA) * 2 + lmCol;

    int rt, ch;
    decode_unit(vStart, rt, ch);

    // prologue: A(rt0) + B(ch0) cp.async; pack bits(u0) -> buf0
    {
#pragma unroll
        for (int i = 0; i < 16; i++) {
            int idx = i * 256 + tid;
            int r = idx >> 5, q = idx & 31;
            cp16(&As[r * SA + q * 8], &g_fn[(size_t)(rt * BM + r) * DD + q * 8]);
            cp16(&B0[r * SA + q * 8], &g_fn[(size_t)(ch * BM + r) * DD + q * 8]);
        }
        cp_commit();
        int nsteps0 = (rt == ch) ? 32 : 64;
        float4 pk[8];
        for (int w0 = 0; w0 < nsteps0; w0 += 8) {
            pack_issue(pk, pmask, nmask, w0, rt, ch, warp, lane);
            pack_consume(pk, bitsAll, w0, warp, lane);
        }
    }

    const int jsel    = (tg & 1) * 2;
    const int bshift0 = wn * 16 + (tg >> 1);
    const uint32_t cntM = 0x5555u << bshift0;

    for (int v = vStart; v < vEnd; v++) {
        const int buf = (v - vStart) & 1;
        const uint32_t bcB = buf ? b1Base : b0Base;
        __nv_bfloat16* Bn  = buf ? B0 : B1;
        uint32_t* bitsC = bitsAll + buf * 2048;
        uint32_t* bitsN = bitsAll + (buf ^ 1) * 2048;

        cp_wait_all();
        __syncthreads();   // tiles + bit STS visible; prior epilogue done with bitsN

        const bool hasNext = (v + 1 < vEnd);
        int nrt = rt, nch = ch + 1;
        if (nch == 32) { nrt = rt + 1; nch = nrt; }
        const int nsteps = (nrt == nch) ? 32 : 64;

        if (hasNext && nrt == rt) {   // B(u+1) streams during MMA + epilogue
#pragma unroll
            for (int i = 0; i < 16; i++) {
                int idx = i * 256 + tid;
                int r = idx >> 5, q = idx & 31;
                cp16(&Bn[r * SA + q * 8], &g_fn[(size_t)(nch * BM + r) * DD + q * 8]);
            }
            cp_commit();
        }

        // --- MMA (16 k-steps) with pack waves for u+1 at 8 interleave points ---
        float acc[2][8][4];
#pragma unroll
        for (int mi = 0; mi < 2; mi++)
#pragma unroll
            for (int ni = 0; ni < 8; ni++)
#pragma unroll
                for (int k = 0; k < 4; k++) acc[mi][ni][k] = 0.f;

        float4 pk[8];
        if (hasNext) pack_issue(pk, pmask, nmask, 0, nrt, nch, warp, lane);

#pragma unroll
        for (int kp = 0; kp < 8; kp++) {
#pragma unroll
            for (int k2 = 0; k2 < 2; k2++) {
                const uint32_t kbB = (uint32_t)(kp * 32 + k2 * 16) * 2;
                uint32_t a[2][4];
#pragma unroll
                for (int mi = 0; mi < 2; mi++)
                    ldsm_x4(a[mi][0], a[mi][1], a[mi][2], a[mi][3], asBase + aOff[mi] + kbB);
                uint32_t br[4][4];
#pragma unroll
                for (int p = 0; p < 4; p++)
                    ldsm_x4(br[p][0], br[p][1], br[p][2], br[p][3], bcB + bOff[p] + kbB);
#pragma unroll
                for (int ni = 0; ni < 8; ni++) {
                    uint32_t b0 = br[ni >> 1][ni & 1];
                    uint32_t b1 = br[ni >> 1][(ni & 1) + 2];
#pragma unroll
                    for (int mi = 0; mi < 2; mi++) {
                        asm volatile(
                            "mma.sync.aligned.m16n8k16.row.col.f32.bf16.bf16.f32 "
                            "{%0,%1,%2,%3}, {%4,%5,%6,%7}, {%8,%9}, {%0,%1,%2,%3};"
                            : "+f"(acc[mi][ni][0]), "+f"(acc[mi][ni][1]),
                              "+f"(acc[mi][ni][2]), "+f"(acc[mi][ni][3])
                            : "r"(a[mi][0]), "r"(a[mi][1]), "r"(a[mi][2]), "r"(a[mi][3]),
                              "r"(b0), "r"(b1));
                    }
                }
            }
            if (hasNext) {
                int w0 = kp * 8;
                if (w0 < nsteps) {
                    pack_consume(pk, bitsN, w0, warp, lane);
                    if (w0 + 8 < nsteps)
                        pack_issue(pk, pmask, nmask, w0 + 8, nrt, nch, warp, lane);
                }
            }
        }

        if (hasNext && nrt != rt) {   // rt-crossing: reload A (+B) after MMA drains
            __syncthreads();          // uniform: all warps done reading As
#pragma unroll
            for (int i = 0; i < 16; i++) {
                int idx = i * 256 + tid;
                int r = idx >> 5, q = idx & 31;
                cp16(&As[r * SA + q * 8], &g_fn[(size_t)(nrt * BM + r) * DD + q * 8]);
                cp16(&Bn[r * SA + q * 8], &g_fn[(size_t)(nch * BM + r) * DD + q * 8]);
            }
            cp_commit();
        }

        // --- epilogue NORMAL: rows of rt-tile, masks tileN (bitsC[0],[512]) ---
#pragma unroll
        for (int mi = 0; mi < 2; mi++) {
#pragma unroll
            for (int h = 0; h < 2; h++) {
                int r  = wm * 32 + mi * 16 + h * 8 + g;
                int ig = rt * BM + r;
                uint2 pw = *(const uint2*)&bitsC[r * 4 + jsel];
                uint2 nw = *(const uint2*)&bitsC[512 + r * 4 + jsel];
                int d = ig - ch * 128;                   // diag only when rt==ch
                if ((unsigned)d < 128u) {
                    int dj = d & 3;
                    uint32_t clr = ~(1u << (d >> 2));
                    if (dj == jsel)     { pw.x &= clr; nw.x &= clr; }
                    if (dj == jsel + 1) { pw.y &= clr; nw.y &= clr; }
                }
                float cnt = (float)(__popc(pw.x & cntM) + __popc(pw.y & cntM));
                float neg = 0.f, pcs = 0.f;
#pragma unroll
                for (int ni = 0; ni < 8; ni++) {
                    int bs = bshift0 + ni * 2;
                    float c0 = acc[mi][ni][h * 2 + 0] * INV_T;
                    float c1 = acc[mi][ni][h * 2 + 1] * INV_T;
                    float e0 = fast_expf(c0);
                    float e1 = fast_expf(c1);
                    if ((nw.x >> bs) & 1) neg += e0;
                    if ((nw.y >> bs) & 1) neg += e1;
                    if ((pw.x >> bs) & 1) pcs += c0;
                    if ((pw.y >> bs) & 1) pcs += c1;
                }
                neg += __shfl_xor_sync(0xffffffffu, neg, 1);
                pcs += __shfl_xor_sync(0xffffffffu, pcs, 1);
                cnt += __shfl_xor_sync(0xffffffffu, cnt, 1);
                neg += __shfl_xor_sync(0xffffffffu, neg, 2);
                pcs += __shfl_xor_sync(0xffffffffu, pcs, 2);
                cnt += __shfl_xor_sync(0xffffffffu, cnt, 2);
                if (tg == 0) {
                    int sl = ig * 64 + ch * 2 + wn;
                    g_negP[sl] = neg;
                    g_pcsP[sl] = pcs;
                    g_cntP[sl] = cnt;
                }
            }
        }

        // --- epilogue TRANSPOSED (rt != ch): rows of ch-tile, masks tileT ---
        if (rt != ch) {
#pragma unroll
            for (int ni = 0; ni < 8; ni++) {
#pragma unroll
                for (int b = 0; b < 2; b++) {
                    int j = wn * 64 + ni * 8 + tg * 2 + b;     // local row in ch-tile
                    uint32_t pwT = bitsC[1024 + j * 4 + (g & 3)];
                    uint32_t nwT = bitsC[1536 + j * 4 + (g & 3)];
                    int p0 = wm * 8 + (g >> 2);
                    float cntT = (float)__popc(pwT & (0x55u << p0));
                    float negT = 0.f, pcsT = 0.f;
#pragma unroll
                    for (int mi = 0; mi < 2; mi++)
#pragma unroll
                        for (int h = 0; h < 2; h++) {
                            float c = acc[mi][ni][h * 2 + b] * INV_T;
                            float e = fast_expf(c);
                            int pos = p0 + mi * 4 + h * 2;
                            if ((nwT >> pos) & 1) negT += e;
                            if ((pwT >> pos) & 1) pcsT += c;
                        }
                    // reduce across the 8 g-lanes (same tg)
                    negT += __shfl_xor_sync(0xffffffffu, negT, 4);
                    pcsT += __shfl_xor_sync(0xffffffffu, pcsT, 4);
                    cntT += __shfl_xor_sync(0xffffffffu, cntT, 4);
                    negT += __shfl_xor_sync(0xffffffffu, negT, 8);
                    pcsT += __shfl_xor_sync(0xffffffffu, pcsT, 8);
                    cntT += __shfl_xor_sync(0xffffffffu, cntT, 8);
                    negT += __shfl_xor_sync(0xffffffffu, negT, 16);
                    pcsT += __shfl_xor_sync(0xffffffffu, pcsT, 16);
                    cntT += __shfl_xor_sync(0xffffffffu, cntT, 16);
                    if (lane < 4) {    // g == 0, lane == tg
                        int jg = ch * 128 + j;
                        int sl = jg * 128 + rt * 4 + wm;
                        g_negT[sl] = negT;
                        g_pcsT[sl] = pcsT;
                        g_cntT[sl] = cntT;
                    }
                }
            }
        }

        rt = nrt; ch = nch;
    }
}

// ---------------------------------------------------------------------------
// Kernel 3: per-row loss (merge 64 normal + 128 T slots, row-major -> float4)
//           + block reduce; last-done block sums 16 partials.
// ---------------------------------------------------------------------------
__global__ void __launch_bounds__(256) rowloss_kernel(float* __restrict__ out) {
    __shared__ float red[256];
    int i = blockIdx.x * 256 + threadIdx.x;
    float neg = 0.f, pcs = 0.f, cnt = 0.f;
    const float4* n4 = (const float4*)&g_negP[i * 64];
    const float4* p4 = (const float4*)&g_pcsP[i * 64];
    const float4* c4 = (const float4*)&g_cntP[i * 64];
#pragma unroll 4
    for (int k = 0; k < 16; k++) {
        float4 a = n4[k]; neg += (a.x + a.y) + (a.z + a.w);
        float4 b = p4[k]; pcs += (b.x + b.y) + (b.z + b.w);
        float4 c = c4[k]; cnt += (c.x + c.y) + (c.z + c.w);
    }
    const float4* nT = (const float4*)&g_negT[i * 128];
    const float4* pT = (const float4*)&g_pcsT[i * 128];
    const float4* cT = (const float4*)&g_cntT[i * 128];
#pragma unroll 4
    for (int k = 0; k < 32; k++) {
        float4 a = nT[k]; neg += (a.x + a.y) + (a.z + a.w);
        float4 b = pT[k]; pcs += (b.x + b.y) + (b.z + b.w);
        float4 c = cT[k]; cnt += (c.x + c.y) + (c.z + c.w);
    }
    float t = 0.f;
    if (cnt > 0.f) t = (pcs - cnt * logf(fmaxf(neg, 1e-30f))) / cnt;
    red[threadIdx.x] = t;
    __syncthreads();
    for (int o = 128; o; o >>= 1) {
        if (threadIdx.x < o) red[threadIdx.x] += red[threadIdx.x + o];
        __syncthreads();
    }
    if (threadIdx.x == 0) {
        g_blockSum[blockIdx.x] = red[0];
        __threadfence();
        unsigned old = atomicInc(&g_ctr, 15u);   // wraps to 0 after 16th arrival
        if (old == 15u) {
            float v = 0.f;
#pragma unroll
            for (int b = 0; b < 16; b++) v += g_blockSum[b];
            out[0] = -v / (float)NN;
        }
    }
}

// ---------------------------------------------------------------------------
extern "C" void kernel_launch(void* const* d_in, const int* in_sizes, int n_in,
                              void* d_out, int out_size) {
    const float* feat = (const float*)d_in[0];
    const float* pm   = (const float*)d_in[1];
    const float* nm   = (const float*)d_in[2];
    float* out = (float*)d_out;

    cudaFuncSetAttribute(ssntx_main_kernel,
                         cudaFuncAttributeMaxDynamicSharedMemorySize, SMEM_TOTAL);

    normalize_kernel<<<NN / 8, 256>>>(feat);
    ssntx_main_kernel<<<GRID, 256, SMEM_TOTAL>>>(pm, nm);
    rowloss_kernel<<<16, 256>>>(out);
}

// round 17
// speedup vs baseline: 1.0844x; 1.0844x over previous
#include <cuda_runtime.h>
#include <cuda_bf16.h>
#include <stdint.h>

#define NN 4096
#define DD 256
#define BM 128
#define BN 128
#define SA 264          // bf16 elems per padded smem row (256+8)
#define NCHUNKS 32
#define NROWT   32
#define NUNITS  (NCHUNKS * NROWT)
#define GRID 148
#define THREADS 512
#define INV_T 14.285714285714286f

// smem: A | B0 | B1 | bit tiles (2 bufs x 2 masks x 512 words)
#define BITS_OFF 202752
#define SMEM_TOTAL (202752 + 8192)

// scratch (no allocations allowed -> device globals)
__device__ __nv_bfloat16 g_fn[NN * DD];
__device__ float g_negP[NN * 128];   // [row][ch*4+wn]
__device__ float g_pcsP[NN * 128];
__device__ float g_cntP[NN * 128];
__device__ float g_blockSum[16];
__device__ unsigned g_ctr = 0;       // self-resetting via atomicInc wrap

// ---------------------------------------------------------------------------
__device__ __forceinline__ float fast_expf(float x) {
    float y = x * 1.4426950408889634f;
    float n = rintf(y);
    float f = y - n;
    float p = 1.3333558146e-3f;
    p = fmaf(p, f, 9.6181291076e-3f);
    p = fmaf(p, f, 5.5504108664e-2f);
    p = fmaf(p, f, 2.4022650696e-1f);
    p = fmaf(p, f, 6.9314718056e-1f);
    p = fmaf(p, f, 1.0f);
    int ni = (int)n;
    return p * __int_as_float((ni + 127) << 23);
}

__device__ __forceinline__ void cp16(void* s, const void* g) {
    uint32_t sa = (uint32_t)__cvta_generic_to_shared(s);
    asm volatile("cp.async.cg.shared.global [%0], [%1], 16;\n" :: "r"(sa), "l"(g));
}
__device__ __forceinline__ void cp_commit()  { asm volatile("cp.async.commit_group;\n" ::: "memory"); }
__device__ __forceinline__ void cp_wait_all(){ asm volatile("cp.async.wait_group 0;\n" ::: "memory"); }

__device__ __forceinline__ void ldsm_x4(uint32_t& r0, uint32_t& r1, uint32_t& r2,
                                        uint32_t& r3, uint32_t saddr) {
    asm volatile("ldmatrix.sync.aligned.m8n8.x4.shared.b16 {%0,%1,%2,%3}, [%4];"
                 : "=r"(r0), "=r"(r1), "=r"(r2), "=r"(r3) : "r"(saddr));
}

// ---- mask pack (16 warps): steps s in [0,16); mask m=s>>3, row-iter i=s&7;
//      warp w owns rows w*8+i. Bit tile: word rowLocal*4+(col&3), bit col>>2.
__device__ __forceinline__ void pack_issue(float4* pk, const float* pmask,
                                           const float* nmask, int w0,
                                           int rowBase, int colBase, int warp, int lane) {
#pragma unroll
    for (int k = 0; k < 4; k++) {
        int s = w0 + k;
        const float* base = (s & 8) ? nmask : pmask;
        const float* src = base + (size_t)(rowBase + warp * 8 + (s & 7)) * NN
                         + colBase + lane * 4;
        pk[k] = __ldcs((const float4*)src);
    }
}
__device__ __forceinline__ void pack_consume(const float4* pk, uint32_t* bits,
                                             int w0, int warp, int lane) {
#pragma unroll
    for (int k = 0; k < 4; k++) {
        int s = w0 + k;
        uint32_t b0 = __ballot_sync(0xffffffffu, pk[k].x != 0.f);
        uint32_t b1 = __ballot_sync(0xffffffffu, pk[k].y != 0.f);
        uint32_t b2 = __ballot_sync(0xffffffffu, pk[k].z != 0.f);
        uint32_t b3 = __ballot_sync(0xffffffffu, pk[k].w != 0.f);
        if (lane == 0) {
            int m = (s >> 3) & 1, i = s & 7;
            *(uint4*)&bits[m * 512 + (warp * 8 + i) * 4] = make_uint4(b0, b1, b2, b3);
        }
    }
}

// ---------------------------------------------------------------------------
// Kernel 1: row-normalize features -> bf16
// ---------------------------------------------------------------------------
__global__ void __launch_bounds__(256) normalize_kernel(const float* __restrict__ f) {
    int row  = blockIdx.x * 8 + (threadIdx.x >> 5);
    int lane = threadIdx.x & 31;
    const float4* src = (const float4*)(f + (size_t)row * DD);
    float4 v0 = src[lane * 2];
    float4 v1 = src[lane * 2 + 1];
    float ss = v0.x * v0.x;
    ss = fmaf(v0.y, v0.y, ss); ss = fmaf(v0.z, v0.z, ss); ss = fmaf(v0.w, v0.w, ss);
    ss = fmaf(v1.x, v1.x, ss); ss = fmaf(v1.y, v1.y, ss);
    ss = fmaf(v1.z, v1.z, ss); ss = fmaf(v1.w, v1.w, ss);
#pragma unroll
    for (int o = 16; o; o >>= 1) ss += __shfl_xor_sync(0xffffffffu, ss, o);
    float s = 1.0f / fmaxf(sqrtf(ss), 1e-8f);
    __nv_bfloat162 h[4];
    h[0] = __floats2bfloat162_rn(v0.x * s, v0.y * s);
    h[1] = __floats2bfloat162_rn(v0.z * s, v0.w * s);
    h[2] = __floats2bfloat162_rn(v1.x * s, v1.y * s);
    h[3] = __floats2bfloat162_rn(v1.z * s, v1.w * s);
    *(uint4*)&g_fn[(size_t)row * DD + lane * 8] = *(uint4*)h;
}

// ---------------------------------------------------------------------------
// Kernel 2: persistent mma.sync GEMM, 512 threads (16 warps, 4/SMSP), warp
// tile 32x32; masks packed in-kernel under the MMA (own-region partition).
// ---------------------------------------------------------------------------
__global__ void __launch_bounds__(THREADS, 1)
ssntx_main_kernel(const float* __restrict__ pmask, const float* __restrict__ nmask) {
    extern __shared__ unsigned char smem[];
    __nv_bfloat16* As = (__nv_bfloat16*)smem;
    __nv_bfloat16* B0 = (__nv_bfloat16*)(smem + BM * SA * 2);
    __nv_bfloat16* B1 = (__nv_bfloat16*)(smem + 2 * BM * SA * 2);
    uint32_t* bitsAll = (uint32_t*)(smem + BITS_OFF);   // [buf][mask][512 words]

    const int tid  = threadIdx.x;
    const int lane = tid & 31;
    const int warp = tid >> 5;
    const int g    = lane >> 2;
    const int tg   = lane & 3;
    const int wm   = warp >> 2;      // 0..3 -> 32-row band
    const int wn   = warp & 3;       // 0..3 -> 32-col band

    const int uStart = (int)(((long long)blockIdx.x       * NUNITS) / GRID);
    const int uEnd   = (int)(((long long)(blockIdx.x + 1) * NUNITS) / GRID);

    const uint32_t asBase = (uint32_t)__cvta_generic_to_shared(As);
    const uint32_t b0Base = (uint32_t)__cvta_generic_to_shared(B0);
    const uint32_t b1Base = (uint32_t)__cvta_generic_to_shared(B1);
    const uint32_t lmCol  = (uint32_t)((lane >> 4) * 8) * 2;
    uint32_t aOff[2], bOff[2];
#pragma unroll
    for (int mi = 0; mi < 2; mi++)
        aOff[mi] = (uint32_t)((wm * 32 + mi * 16 + (lane & 15)) * SA) * 2 + lmCol;
#pragma unroll
    for (int p = 0; p < 2; p++)
        bOff[p] = (uint32_t)((wn * 32 + p * 16 + (lane & 15)) * SA) * 2 + lmCol;

    // prologue: A(rt0) + B(u0) cp.async; pack bits(u0) -> buf0
    {
        int rt0 = uStart >> 5, ch0 = uStart & 31;
#pragma unroll
        for (int i = 0; i < 8; i++) {
            int idx = i * THREADS + tid;
            int r = idx >> 5, q = idx & 31;
            cp16(&As[r * SA + q * 8], &g_fn[(size_t)(rt0 * BM + r) * DD + q * 8]);
            cp16(&B0[r * SA + q * 8], &g_fn[(size_t)(ch0 * BN + r) * DD + q * 8]);
        }
        cp_commit();
        float4 pk[4];
#pragma unroll
        for (int w0 = 0; w0 < 16; w0 += 4) {
            pack_issue(pk, pmask, nmask, w0, rt0 * BM, ch0 * BN, warp, lane);
            pack_consume(pk, bitsAll, w0, warp, lane);
        }
    }

    const int jsel    = (tg & 1) * 2;             // word pair select
    const int bshift0 = wn * 8 + (tg >> 1);       // bit base for ni=0
    const uint32_t cntM = 0x55u << bshift0;       // 4 even-ni bits per word

    for (int u = uStart; u < uEnd; u++) {
        const int rt = u >> 5, ch = u & 31;
        const int rowBase = rt * BM;
        const int buf = (u - uStart) & 1;
        const uint32_t bcB = buf ? b1Base : b0Base;
        __nv_bfloat16* Bn  = buf ? B0 : B1;
        uint32_t* bitsC = bitsAll + buf * 1024;
        uint32_t* bitsN = bitsAll + (buf ^ 1) * 1024;

        cp_wait_all();
        __syncthreads();   // tiles + bit STS visible; prior epilogue done with bitsN

        const bool hasNext = (u + 1 < uEnd);
        const int  nrt = (u + 1) >> 5, nch = (u + 1) & 31;

        if (hasNext && nrt == rt) {
#pragma unroll
            for (int i = 0; i < 8; i++) {
                int idx = i * THREADS + tid;
                int r = idx >> 5, q = idx & 31;
                cp16(&Bn[r * SA + q * 8], &g_fn[(size_t)(nch * BN + r) * DD + q * 8]);
            }
            cp_commit();
        }

        // --- 32x32 warp-tile MMA over 16 k-steps; pack waves at k-quarters ---
        float acc[2][4][4];
#pragma unroll
        for (int mi = 0; mi < 2; mi++)
#pragma unroll
            for (int ni = 0; ni < 4; ni++)
#pragma unroll
                for (int k = 0; k < 4; k++) acc[mi][ni][k] = 0.f;

        float4 pk[4];
        if (hasNext) pack_issue(pk, pmask, nmask, 0, nrt * BM, nch * BN, warp, lane);

#pragma unroll
        for (int kq = 0; kq < 4; kq++) {
#pragma unroll
            for (int kb2 = 0; kb2 < 4; kb2++) {
                const uint32_t kbB = (uint32_t)(kq * 64 + kb2 * 16) * 2;
                uint32_t a[2][4];
#pragma unroll
                for (int mi = 0; mi < 2; mi++)
                    ldsm_x4(a[mi][0], a[mi][1], a[mi][2], a[mi][3], asBase + aOff[mi] + kbB);
                uint32_t br[2][4];
#pragma unroll
                for (int p = 0; p < 2; p++)
                    ldsm_x4(br[p][0], br[p][1], br[p][2], br[p][3], bcB + bOff[p] + kbB);
#pragma unroll
                for (int ni = 0; ni < 4; ni++) {
                    uint32_t b0 = br[ni >> 1][ni & 1];
                    uint32_t b1 = br[ni >> 1][(ni & 1) + 2];
#pragma unroll
                    for (int mi = 0; mi < 2; mi++) {
                        asm volatile(
                            "mma.sync.aligned.m16n8k16.row.col.f32.bf16.bf16.f32 "
                            "{%0,%1,%2,%3}, {%4,%5,%6,%7}, {%8,%9}, {%0,%1,%2,%3};"
                            : "+f"(acc[mi][ni][0]), "+f"(acc[mi][ni][1]),
                              "+f"(acc[mi][ni][2]), "+f"(acc[mi][ni][3])
                            : "r"(a[mi][0]), "r"(a[mi][1]), "r"(a[mi][2]), "r"(a[mi][3]),
                              "r"(b0), "r"(b1));
                    }
                }
            }
            if (hasNext) {
                pack_consume(pk, bitsN, kq * 4, warp, lane);
                if (kq < 3)
                    pack_issue(pk, pmask, nmask, (kq + 1) * 4, nrt * BM, nch * BN, warp, lane);
            }
        }

        if (hasNext && nrt != rt) {
            __syncthreads();   // uniform: all warps done reading As
#pragma unroll
            for (int i = 0; i < 8; i++) {
                int idx = i * THREADS + tid;
                int r = idx >> 5, q = idx & 31;
                cp16(&As[r * SA + q * 8], &g_fn[(size_t)(nrt * BM + r) * DD + q * 8]);
                cp16(&Bn[r * SA + q * 8], &g_fn[(size_t)(nch * BN + r) * DD + q * 8]);
            }
            cp_commit();
        }

        // --- epilogue: 4 row-contexts (mi,h); 32 cols per warp band ---
#pragma unroll
        for (int mi = 0; mi < 2; mi++) {
#pragma unroll
            for (int h = 0; h < 2; h++) {
                int r  = wm * 32 + mi * 16 + h * 8 + g;
                int ig = rowBase + r;
                uint2 pw = *(const uint2*)&bitsC[r * 4 + jsel];
                uint2 nw = *(const uint2*)&bitsC[512 + r * 4 + jsel];
                int d = ig - ch * 128;
                if ((unsigned)d < 128u) {
                    int dj = d & 3;
                    uint32_t clr = ~(1u << (d >> 2));
                    if (dj == jsel)     { pw.x &= clr; nw.x &= clr; }
                    if (dj == jsel + 1) { pw.y &= clr; nw.y &= clr; }
                }
                float cnt = (float)(__popc(pw.x & cntM) + __popc(pw.y & cntM));
                float neg = 0.f, pcs = 0.f;
#pragma unroll
                for (int ni = 0; ni < 4; ni++) {
                    int bs = bshift0 + ni * 2;
                    float c0 = acc[mi][ni][h * 2 + 0] * INV_T;
                    float c1 = acc[mi][ni][h * 2 + 1] * INV_T;
                    float e0 = fast_expf(c0);
                    float e1 = fast_expf(c1);
                    if ((nw.x >> bs) & 1) neg += e0;
                    if ((nw.y >> bs) & 1) neg += e1;
                    if ((pw.x >> bs) & 1) pcs += c0;
                    if ((pw.y >> bs) & 1) pcs += c1;
                }
                neg += __shfl_xor_sync(0xffffffffu, neg, 1);
                pcs += __shfl_xor_sync(0xffffffffu, pcs, 1);
                cnt += __shfl_xor_sync(0xffffffffu, cnt, 1);
                neg += __shfl_xor_sync(0xffffffffu, neg, 2);
                pcs += __shfl_xor_sync(0xffffffffu, pcs, 2);
                cnt += __shfl_xor_sync(0xffffffffu, cnt, 2);
                if (tg == 0) {
                    int slot = ig * 128 + ch * 4 + wn;
                    g_negP[slot] = neg;
                    g_pcsP[slot] = pcs;
                    g_cntP[slot] = cnt;
                }
            }
        }
    }
}

// ---------------------------------------------------------------------------
// Kernel 3: per-row loss (float4 over 128 row-major slots) + block reduce;
// last-done block sums 16 partials.
// ---------------------------------------------------------------------------
__global__ void __launch_bounds__(256) rowloss_kernel(float* __restrict__ out) {
    __shared__ float red[256];
    int i = blockIdx.x * 256 + threadIdx.x;
    float neg = 0.f, pcs = 0.f, cnt = 0.f;
    const float4* n4 = (const float4*)&g_negP[i * 128];
    const float4* p4 = (const float4*)&g_pcsP[i * 128];
    const float4* c4 = (const float4*)&g_cntP[i * 128];
#pragma unroll 4
    for (int k = 0; k < 32; k++) {
        float4 a = n4[k]; neg += (a.x + a.y) + (a.z + a.w);
        float4 b = p4[k]; pcs += (b.x + b.y) + (b.z + b.w);
        float4 c = c4[k]; cnt += (c.x + c.y) + (c.z + c.w);
    }
    float t = 0.f;
    if (cnt > 0.f) t = (pcs - cnt * logf(fmaxf(neg, 1e-30f))) / cnt;
    red[threadIdx.x] = t;
    __syncthreads();
    for (int o = 128; o; o >>= 1) {
        if (threadIdx.x < o) red[threadIdx.x] += red[threadIdx.x + o];
        __syncthreads();
    }
    if (threadIdx.x == 0) {
        g_blockSum[blockIdx.x] = red[0];
        __threadfence();
        unsigned old = atomicInc(&g_ctr, 15u);   // wraps to 0 after 16th arrival
        if (old == 15u) {
            float v = 0.f;
#pragma unroll
            for (int b = 0; b < 16; b++) v += g_blockSum[b];
            out[0] = -v / (float)NN;
        }
    }
}

// ---------------------------------------------------------------------------
extern "C" void kernel_launch(void* const* d_in, const int* in_sizes, int n_in,
                              void* d_out, int out_size) {
    const float* feat = (const float*)d_in[0];
    const float* pm   = (const float*)d_in[1];
    const float* nm   = (const float*)d_in[2];
    float* out = (float*)d_out;

    cudaFuncSetAttribute(ssntx_main_kernel,
                         cudaFuncAttributeMaxDynamicSharedMemorySize, SMEM_TOTAL);

    normalize_kernel<<<NN / 8, 256>>>(feat);
    ssntx_main_kernel<<<GRID, THREADS, SMEM_TOTAL>>>(pm, nm);
    rowloss_kernel<<<16, 256>>>(out);
}